// round 7
// baseline (speedup 1.0000x reference)
#include <cuda_runtime.h>
#include <cuda_bf16.h>
#include <cstdint>

#define BB 8
#define LL 128
#define DD 768
#define TI 4

#define GM (BB * LL)   // 1024
#define GN DD          // 768
#define GK DD          // 768

#define AGG_BLOCKS (BB * (LL / TI))          // 256
#define WSP_BLOCKS ((GN / 64) * (GK / 64))   // 144

// ---------------- global scratch (no allocation allowed) ----------------
__device__ __nv_bfloat16 g_Ahi[GM * GK];
__device__ __nv_bfloat16 g_Alo[GM * GK];
__device__ __nv_bfloat16 g_Whi[GN * GK];   // [n][k]  (W transposed)
__device__ __nv_bfloat16 g_Wlo[GN * GK];

__device__ __forceinline__ uint32_t pack_bf16x2(float a, float b) {
    __nv_bfloat162 h = __floats2bfloat162_rn(a, b);
    return *reinterpret_cast<uint32_t*>(&h);
}

// ---------------------------------------------------------------------------
// Combined kernel 1: blocks [0,256) do agg; blocks [256,400) do W split.
// (R3/R5-proven body — do not disturb)
// ---------------------------------------------------------------------------
__global__ void __launch_bounds__(256, 4)
prep_kernel(const float* __restrict__ text,
            const float* __restrict__ adj,
            const float* __restrict__ dep,
            const float* __restrict__ W,
            __nv_bfloat16* __restrict__ Ahi,
            __nv_bfloat16* __restrict__ Alo,
            __nv_bfloat16* __restrict__ Whi,
            __nv_bfloat16* __restrict__ Wlo)
{
    __shared__ float sh[64 * 65];
    const int tid = threadIdx.x;

    if (blockIdx.x < AGG_BLOCKS) {
        const int b  = blockIdx.x / (LL / TI);
        const int i0 = (blockIdx.x % (LL / TI)) * TI;

        float (*s_adj)[LL] = reinterpret_cast<float (*)[LL]>(sh);
        for (int k = tid; k < TI * LL; k += 256) {
            int ii = k / LL, j = k % LL;
            s_adj[ii][j] = adj[((size_t)b * LL + (i0 + ii)) * LL + j];
        }
        __syncthreads();

        const int d0 = tid;
        float acc[TI][3];
#pragma unroll
        for (int ii = 0; ii < TI; ++ii) { acc[ii][0] = 0.f; acc[ii][1] = 0.f; acc[ii][2] = 0.f; }

        const float* textb = text + (size_t)b * LL * DD;
        const float* depb  = dep  + (size_t)b * LL * LL * DD;

#pragma unroll 2
        for (int j = 0; j < LL; ++j) {
            const float t0 = textb[(size_t)j * DD + d0];
            const float t1 = textb[(size_t)j * DD + d0 + 256];
            const float t2 = textb[(size_t)j * DD + d0 + 512];
            const float* dj = depb + (size_t)j * LL * DD + (size_t)i0 * DD + d0;
#pragma unroll
            for (int ii = 0; ii < TI; ++ii) {
                const float a = s_adj[ii][j];
                const float e0 = dj[ii * DD];
                const float e1 = dj[ii * DD + 256];
                const float e2 = dj[ii * DD + 512];
                acc[ii][0] = fmaf(a, t0 + e0, acc[ii][0]);
                acc[ii][1] = fmaf(a, t1 + e1, acc[ii][1]);
                acc[ii][2] = fmaf(a, t2 + e2, acc[ii][2]);
            }
        }

#pragma unroll
        for (int ii = 0; ii < TI; ++ii) {
#pragma unroll
            for (int p = 0; p < 3; ++p) {
                float v = acc[ii][p];
                __nv_bfloat16 h = __float2bfloat16(v);
                __nv_bfloat16 l = __float2bfloat16(v - __bfloat162float(h));
                size_t idx = ((size_t)b * LL + (i0 + ii)) * (size_t)GK + d0 + 256 * p;
                Ahi[idx] = h;
                Alo[idx] = l;
            }
        }
    } else {
        const int w  = blockIdx.x - AGG_BLOCKS;
        const int n0 = (w % (GN / 64)) * 64;
        const int k0 = (w / (GN / 64)) * 64;
        float (*t)[65] = reinterpret_cast<float (*)[65]>(sh);
        const int tx = tid & 15;
        const int ty = tid >> 4;

#pragma unroll
        for (int i = 0; i < 4; ++i) {
            const int row = ty + 16 * i;
            const float4 v = *reinterpret_cast<const float4*>(
                &W[(size_t)(k0 + row) * GN + n0 + tx * 4]);
            t[row][tx * 4 + 0] = v.x;
            t[row][tx * 4 + 1] = v.y;
            t[row][tx * 4 + 2] = v.z;
            t[row][tx * 4 + 3] = v.w;
        }
        __syncthreads();

#pragma unroll
        for (int i = 0; i < 4; ++i) {
            const int n = ty + 16 * i;
            const int k = tx * 4;
            const float v0 = t[k + 0][n];
            const float v1 = t[k + 1][n];
            const float v2 = t[k + 2][n];
            const float v3 = t[k + 3][n];
            const float h0 = __bfloat162float(__float2bfloat16(v0));
            const float h1 = __bfloat162float(__float2bfloat16(v1));
            const float h2 = __bfloat162float(__float2bfloat16(v2));
            const float h3 = __bfloat162float(__float2bfloat16(v3));
            uint2 hi, lo;
            hi.x = pack_bf16x2(v0, v1);
            hi.y = pack_bf16x2(v2, v3);
            lo.x = pack_bf16x2(v0 - h0, v1 - h1);
            lo.y = pack_bf16x2(v2 - h2, v3 - h3);
            const size_t idx = (size_t)(n0 + n) * GK + k0 + k;
            *reinterpret_cast<uint2*>(Whi + idx) = hi;
            *reinterpret_cast<uint2*>(Wlo + idx) = lo;
        }
    }
}

// ---------------------------------------------------------------------------
// Kernel 2: HMMA bf16 GEMM, hi/lo 3-pass, fp32 accum.
// 64x48 CTA tile -> 256 CTAs, 2 CTAs/SM co-resident (one wave with overlap).
// BK=64, 2-stage cp.async. 8 warps: warp tile 16x24 (4 m-warps x 2 n-warps).
// ---------------------------------------------------------------------------
#define BM 64
#define BN 48
#define BK 64
#define NCH (GK / BK)            // 12
#define PITCH 144
#define A_TILE_B (BM * PITCH)    // 9216
#define B_TILE_B (BN * PITCH)    // 6912
#define STAGE_B (2 * A_TILE_B + 2 * B_TILE_B)   // 32256
#define GEMM_SMEM (2 * STAGE_B)                 // 64512

__device__ __forceinline__ uint32_t smem_u32(const void* p) {
    uint32_t a;
    asm("{ .reg .u64 t; cvta.to.shared.u64 t, %1; cvt.u32.u64 %0, t; }" : "=r"(a) : "l"(p));
    return a;
}
__device__ __forceinline__ void cp_async16(uint32_t dst, const void* src) {
    asm volatile("cp.async.cg.shared.global [%0], [%1], 16;" :: "r"(dst), "l"(src));
}
#define CP_COMMIT() asm volatile("cp.async.commit_group;")
#define CP_WAIT1()  asm volatile("cp.async.wait_group 1;")

__device__ __forceinline__ void ldsm_x4(uint32_t* r, uint32_t addr) {
    asm volatile("ldmatrix.sync.aligned.m8n8.x4.shared.b16 {%0,%1,%2,%3}, [%4];"
                 : "=r"(r[0]), "=r"(r[1]), "=r"(r[2]), "=r"(r[3]) : "r"(addr));
}
__device__ __forceinline__ void ldsm_x2(uint32_t* r, uint32_t addr) {
    asm volatile("ldmatrix.sync.aligned.m8n8.x2.shared.b16 {%0,%1}, [%2];"
                 : "=r"(r[0]), "=r"(r[1]) : "r"(addr));
}
__device__ __forceinline__ void mma_bf16(float* c, const uint32_t* a, const uint32_t* b) {
    asm volatile(
        "mma.sync.aligned.m16n8k16.row.col.f32.bf16.bf16.f32 "
        "{%0,%1,%2,%3}, {%4,%5,%6,%7}, {%8,%9}, {%0,%1,%2,%3};"
        : "+f"(c[0]), "+f"(c[1]), "+f"(c[2]), "+f"(c[3])
        : "r"(a[0]), "r"(a[1]), "r"(a[2]), "r"(a[3]), "r"(b[0]), "r"(b[1]));
}

__global__ void __launch_bounds__(256, 2)
gemm_hmma(const __nv_bfloat16* __restrict__ Ahi,
          const __nv_bfloat16* __restrict__ Alo,
          const __nv_bfloat16* __restrict__ Whi,
          const __nv_bfloat16* __restrict__ Wlo,
          const float* __restrict__ bias,
          float* __restrict__ out)
{
    extern __shared__ char smem[];
    const uint32_t sbase = smem_u32(smem);
    const int tid = threadIdx.x;
    const int wid = tid >> 5;
    const int lid = tid & 31;

    const int n0 = blockIdx.x * BN;
    const int m0 = blockIdx.y * BM;
    const int warp_m = wid >> 1;     // 0..3  (16 rows each)
    const int warp_n = wid & 1;      // 0..1  (24 cols each)

    const int l_row = tid >> 3;      // 0..31
    const int l_c16 = tid & 7;

    float acc[3][4];
#pragma unroll
    for (int nt = 0; nt < 3; ++nt)
#pragma unroll
        for (int r = 0; r < 4; ++r) acc[nt][r] = 0.f;

    auto load_chunk = [&](int c, int s) {
        const int k0 = c * BK;
        const uint32_t stage = sbase + s * STAGE_B;
        const uint32_t tAhi = stage;
        const uint32_t tAlo = stage + A_TILE_B;
        const uint32_t tBhi = stage + 2 * A_TILE_B;
        const uint32_t tBlo = stage + 2 * A_TILE_B + B_TILE_B;
#pragma unroll
        for (int i = 0; i < 2; ++i) {
            const int row = l_row + 32 * i;
            const uint32_t doff = (uint32_t)(row * PITCH + l_c16 * 16);
            const size_t ga = (size_t)(m0 + row) * GK + k0 + l_c16 * 8;
            cp_async16(tAhi + doff, Ahi + ga);
            cp_async16(tAlo + doff, Alo + ga);
        }
        {
            const int row = l_row;                       // rows 0..31
            const uint32_t doff = (uint32_t)(row * PITCH + l_c16 * 16);
            const size_t gb = (size_t)(n0 + row) * GK + k0 + l_c16 * 8;
            cp_async16(tBhi + doff, Whi + gb);
            cp_async16(tBlo + doff, Wlo + gb);
        }
        if (tid < 128) {                                 // rows 32..47
            const int row = 32 + (tid >> 3);
            const uint32_t doff = (uint32_t)(row * PITCH + l_c16 * 16);
            const size_t gb = (size_t)(n0 + row) * GK + k0 + l_c16 * 8;
            cp_async16(tBhi + doff, Whi + gb);
            cp_async16(tBlo + doff, Wlo + gb);
        }
    };

    load_chunk(0, 0); CP_COMMIT();
    load_chunk(1, 1); CP_COMMIT();

    // A ldsm x4 (16 rows): g0 r0-7 c0, g1 r8-15 c0, g2 r0-7 c16, g3 r8-15 c16
    const int a_sub = lid >> 3;
    const int a_row_off = (a_sub & 1) * 8 + (lid & 7);
    const int a_col_off = (a_sub >> 1) * 16;
    // B ldsm x4 (first 16 n-rows): g0 r0-7 c0, g1 r0-7 c16, g2 r8-15 c0, g3 r8-15 c16
    const int b_sub = lid >> 3;
    const int b_row_off = (b_sub >> 1) * 8 + (lid & 7);
    const int b_col_off = (b_sub & 1) * 16;
    // B ldsm x2 (rows 16-23)
    const int b2_row_off = 16 + (lid & 7);
    const int b2_col_off = ((lid >> 3) & 1) * 16;

    for (int c = 0; c < NCH; ++c) {
        CP_WAIT1();
        __syncthreads();

        const uint32_t stage = sbase + (c & 1) * STAGE_B;
        const uint32_t tAhi = stage;
        const uint32_t tAlo = stage + A_TILE_B;
        const uint32_t tBhi = stage + 2 * A_TILE_B;
        const uint32_t tBlo = stage + 2 * A_TILE_B + B_TILE_B;

#pragma unroll
        for (int ks = 0; ks < BK / 16; ++ks) {
            const int kb = ks * 32;
            uint32_t ah[4], al[4], bh[6], bl[6];
            {
                const uint32_t ao =
                    (uint32_t)((warp_m * 16 + a_row_off) * PITCH + kb + a_col_off);
                ldsm_x4(ah, tAhi + ao);
                ldsm_x4(al, tAlo + ao);
            }
            {
                const uint32_t bo =
                    (uint32_t)((warp_n * 24 + b_row_off) * PITCH + kb + b_col_off);
                ldsm_x4(bh, tBhi + bo);
                ldsm_x4(bl, tBlo + bo);
                const uint32_t bo2 =
                    (uint32_t)((warp_n * 24 + b2_row_off) * PITCH + kb + b2_col_off);
                ldsm_x2(bh + 4, tBhi + bo2);
                ldsm_x2(bl + 4, tBlo + bo2);
            }
#pragma unroll
            for (int nt = 0; nt < 3; ++nt) {
                const uint32_t* bhf = &bh[nt * 2];
                const uint32_t* blf = &bl[nt * 2];
                mma_bf16(acc[nt], ah, bhf);
                mma_bf16(acc[nt], ah, blf);
                mma_bf16(acc[nt], al, bhf);
            }
        }
        __syncthreads();

        if (c + 2 < NCH) load_chunk(c + 2, c & 1);
        CP_COMMIT();
    }

    // ---- epilogue: bias + relu ----
    const int col_base = n0 + warp_n * 24 + 2 * (lid & 3);
    const int row_base = m0 + warp_m * 16 + (lid >> 2);
#pragma unroll
    for (int nt = 0; nt < 3; ++nt) {
        const int col = col_base + nt * 8;
        const float2 bv = *reinterpret_cast<const float2*>(&bias[col]);
#pragma unroll
        for (int h = 0; h < 2; ++h) {
            const int row = row_base + h * 8;
            float2 o;
            o.x = fmaxf(acc[nt][2 * h + 0] + bv.x, 0.f);
            o.y = fmaxf(acc[nt][2 * h + 1] + bv.y, 0.f);
            *reinterpret_cast<float2*>(&out[(size_t)row * GN + col]) = o;
        }
    }
}

// ---------------------------------------------------------------------------
extern "C" void kernel_launch(void* const* d_in, const int* in_sizes, int n_in,
                              void* d_out, int out_size)
{
    const float* text = (const float*)d_in[0];
    const float* adj  = (const float*)d_in[1];
    const float* dep  = (const float*)d_in[2];
    const float* W    = (const float*)d_in[3];
    const float* bias = (const float*)d_in[4];
    float* out = (float*)d_out;

    __nv_bfloat16 *Ahi, *Alo, *Whi, *Wlo;
    cudaGetSymbolAddress((void**)&Ahi, g_Ahi);
    cudaGetSymbolAddress((void**)&Alo, g_Alo);
    cudaGetSymbolAddress((void**)&Whi, g_Whi);
    cudaGetSymbolAddress((void**)&Wlo, g_Wlo);

    cudaFuncSetAttribute(gemm_hmma, cudaFuncAttributeMaxDynamicSharedMemorySize, GEMM_SMEM);

    prep_kernel<<<AGG_BLOCKS + WSP_BLOCKS, 256>>>(text, adj, dep, W, Ahi, Alo, Whi, Wlo);
    gemm_hmma<<<dim3(GN / BN, GM / BM), 256, GEMM_SMEM>>>(Ahi, Alo, Whi, Wlo, bias, out);
}